// round 12
// baseline (speedup 1.0000x reference)
#include <cuda_runtime.h>
#include <cuda_bf16.h>
#include <math.h>
#include <stdint.h>

#define NB 16
#define NT 2048
#define ND 256
#define NC 128
#define MAXK 20
#define WLEN 19   // live window elements

typedef unsigned long long ull;

union U2 { float4 f4; ull u[2]; };

#define FMA2(acc, a, b) asm("fma.rn.f32x2 %0, %1, %2, %0;" : "+l"(acc) : "l"(a), "l"(b))
#define PACK2(d, x, y)  asm("mov.b64 %0, {%1, %2};" : "=l"(d) : "f"(x), "f"(y))
#define UNPACK2(x, y, d) asm("mov.b64 {%0, %1}, %2;" : "=f"(x), "=f"(y) : "l"(d))

#define MMA16816(d, a, b) \
    asm("mma.sync.aligned.m16n8k16.row.col.f32.bf16.bf16.f32 " \
        "{%0,%1,%2,%3}, {%4,%5,%6,%7}, {%8,%9}, {%0,%1,%2,%3};" \
        : "+f"((d)[0]), "+f"((d)[1]), "+f"((d)[2]), "+f"((d)[3]) \
        : "r"((a)[0]), "r"((a)[1]), "r"((a)[2]), "r"((a)[3]), \
          "r"((b)[0]), "r"((b)[1]))

// ---------- device scratch ----------
__device__ float g_E[NC * NC];        // exp(trans_lp) row-major, diag 0
__device__ float g_winit[NC];         // exp(init_lp)
__device__ float g_dtab[MAXK * NC];   // exp(len_lp[l-1][c])
__device__ float g_miT[ND * NC];      // (means*inv_var)^T  [d][c]
__device__ float g_cb[NC];            // const - 0.5*mq[c]
__device__ float g_iv[ND];            // 1/cov
__device__ float g_f[(size_t)NB * NT * NC]; // exp(emis - rowmax)
__device__ float g_mu[NB * NT];       // rowmax(emis)

static __device__ __forceinline__ unsigned pbf(float lo, float hi) {
    __nv_bfloat162 t = __floats2bfloat162_rn(lo, hi);  // (.x=lo, .y=hi)
    return *(unsigned*)&t;
}

// ---------- prep_misc: 1 block x 256 ----------
__global__ void prep_misc(const float* __restrict__ means,
                          const float* __restrict__ cov,
                          const float* __restrict__ initlg,
                          const float* __restrict__ lograte) {
    const int t = threadIdx.x;
    const int lane = t & 31, w = t >> 5;
    __shared__ float red[8];
    __shared__ float s_cst;
    __shared__ float s_iv[ND];

    float cv = cov[t];
    float iv = __fdividef(1.0f, cv);
    g_iv[t] = iv;
    s_iv[t] = iv;
    float ls = __logf(cv);
#pragma unroll
    for (int o = 16; o >= 1; o >>= 1)
        ls += __shfl_xor_sync(0xffffffffu, ls, o);
    if (lane == 0) red[w] = ls;
    __syncthreads();
    if (t == 0) {
        float tot = 0.f;
        for (int i = 0; i < 8; ++i) tot += red[i];
        s_cst = -0.5f * (256.0f * 1.8378770664093453f + tot);
    }
    __syncthreads();
    const float cst = s_cst;

    for (int ci = 0; ci < 16; ++ci) {
        int c = ci * 8 + w;
        float p = 0.f;
#pragma unroll
        for (int k = 0; k < 8; ++k) {
            int d = k * 32 + lane;
            float m = means[c * ND + d];
            p = fmaf(m * m, s_iv[d], p);
        }
#pragma unroll
        for (int o = 16; o >= 1; o >>= 1)
            p += __shfl_xor_sync(0xffffffffu, p, o);
        if (lane == 0) g_cb[c] = cst - 0.5f * p;
    }

    if (t < NC) {
        float il = initlg[t];
        float mx = il;
#pragma unroll
        for (int o = 16; o >= 1; o >>= 1)
            mx = fmaxf(mx, __shfl_xor_sync(0xffffffffu, mx, o));
        if (lane == 0) red[w] = mx;
    }
    __syncthreads();
    if (t < NC) {
        float mx = fmaxf(fmaxf(red[0], red[1]), fmaxf(red[2], red[3]));
        float il = initlg[t];
        float ex = __expf(il - mx);
        float s = ex;
#pragma unroll
        for (int o = 16; o >= 1; o >>= 1)
            s += __shfl_xor_sync(0xffffffffu, s, o);
        if (lane == 0) red[4 + w] = s;
        __syncthreads();
        float tot = (red[4] + red[5]) + (red[6] + red[7]);
        g_winit[t] = __fdividef(ex, tot);

        float r = lograte[t];
        float lam = __expf(r);
        float lg = 0.f;
        for (int l = 1; l <= MAXK; ++l) {
            lg += __logf((float)l);
            g_dtab[(l - 1) * NC + t] = __expf(fmaf((float)l, r, -lam) - lg);
        }
    }
}

// ---------- prep_trans: 1 block x 1024 ----------
__global__ __launch_bounds__(1024) void prep_trans(const float* __restrict__ trans) {
    const int t = threadIdx.x;
    const int j = t & 127;
    const int g = t >> 7;
    __shared__ float gmax[8][NC];
    __shared__ float gsum[8][NC];
    __shared__ float colmax[NC], colinv[NC];

    float v[16];
    float mx = -3.0e38f;
#pragma unroll
    for (int k = 0; k < 16; ++k) {
        int i = g * 16 + k;
        float x = trans[i * NC + j];
        if (i == j) x = -1.0e9f;
        v[k] = x;
        mx = fmaxf(mx, x);
    }
    gmax[g][j] = mx;
    __syncthreads();
    if (t < NC) {
        float m = gmax[0][t];
#pragma unroll
        for (int i = 1; i < 8; ++i) m = fmaxf(m, gmax[i][t]);
        colmax[t] = m;
    }
    __syncthreads();
    float cm = colmax[j];
    float ex[16], s = 0.f;
#pragma unroll
    for (int k = 0; k < 16; ++k) {
        ex[k] = __expf(v[k] - cm);
        s += ex[k];
    }
    gsum[g][j] = s;
    __syncthreads();
    if (t < NC) {
        float ss = 0.f;
#pragma unroll
        for (int i = 0; i < 8; ++i) ss += gsum[i][t];
        colinv[t] = __fdividef(1.0f, ss);
    }
    __syncthreads();
    float inv = colinv[j];
#pragma unroll
    for (int k = 0; k < 16; ++k) {
        int i = g * 16 + k;
        g_E[i * NC + j] = (i == j) ? 0.0f : ex[k] * inv;
    }
}

// ---------- prep_miT: 32 blocks x 256 ----------
__global__ void prep_miT(const float* __restrict__ means,
                         const float* __restrict__ cov) {
    __shared__ float tile[32][33];
    const int t = threadIdx.x;
    const int tc = blockIdx.x & 3, td = blockIdx.x >> 2;
    const int c0 = tc * 32, d0 = td * 32;
    const int r = t >> 5, dl = t & 31;

    float iv = __fdividef(1.0f, cov[d0 + dl]);
#pragma unroll
    for (int k = 0; k < 4; ++k) {
        int rr = r + 8 * k;
        tile[rr][dl] = means[(c0 + rr) * ND + d0 + dl] * iv;
    }
    __syncthreads();
#pragma unroll
    for (int k = 0; k < 4; ++k) {
        int dr = r + 8 * k;
        g_miT[(d0 + dr) * NC + c0 + dl] = tile[dl][dr];
    }
}

// ---------- emission GEMM + exp epilogue: 256 blocks x 256, 2 blocks/SM ----------
__global__ __launch_bounds__(256, 2) void emis_kernel(const float* __restrict__ feat) {
    __shared__ float A[128][40];
    __shared__ float Bt[32][132];
    __shared__ float ivs[32];

    const int tid = threadIdx.x;
    const int r0 = blockIdx.x * 128;
    const int cg = tid & 15;
    const int rr = tid >> 4;

    ull acc2[8][4];
#pragma unroll
    for (int i = 0; i < 8; ++i)
#pragma unroll
        for (int k = 0; k < 4; ++k) acc2[i][k] = 0ull;
    float xq[8];
#pragma unroll
    for (int i = 0; i < 8; ++i) xq[i] = 0.f;

    for (int d0 = 0; d0 < ND; d0 += 32) {
        __syncthreads();
#pragma unroll
        for (int k = 0; k < 4; ++k) {
            int i = tid + k * 256;
            int row = i >> 3, q = i & 7;
            *(float4*)&A[row][q * 4] = *(const float4*)&feat[(size_t)(r0 + row) * ND + d0 + q * 4];
        }
#pragma unroll
        for (int k = 0; k < 4; ++k) {
            int i = tid + k * 256;
            int drow = i >> 5, q = i & 31;
            *(float4*)&Bt[drow][q * 4] = *(const float4*)&g_miT[(size_t)(d0 + drow) * NC + q * 4];
        }
        if (tid < 32) ivs[tid] = g_iv[d0 + tid];
        __syncthreads();

#pragma unroll
        for (int u = 0; u < 2; ++u) {
            int dd = cg + u * 16;
            float iv = ivs[dd];
#pragma unroll
            for (int i = 0; i < 8; ++i) {
                float a = A[rr + 16 * i][dd];
                xq[i] = fmaf(a * iv, a, xq[i]);
            }
        }

#pragma unroll 8
        for (int dd = 0; dd < 32; ++dd) {
            U2 b0, b1;
            b0.f4 = *(const float4*)&Bt[dd][cg * 4];
            b1.f4 = *(const float4*)&Bt[dd][64 + cg * 4];
#pragma unroll
            for (int i = 0; i < 8; ++i) {
                float a = A[rr + 16 * i][dd];
                ull aa;
                PACK2(aa, a, a);
                FMA2(acc2[i][0], aa, b0.u[0]);
                FMA2(acc2[i][1], aa, b0.u[1]);
                FMA2(acc2[i][2], aa, b1.u[0]);
                FMA2(acc2[i][3], aa, b1.u[1]);
            }
        }
    }

#pragma unroll
    for (int o = 1; o < 16; o <<= 1) {
#pragma unroll
        for (int i = 0; i < 8; ++i)
            xq[i] += __shfl_xor_sync(0xffffffffu, xq[i], o, 16);
    }

    float cb[8];
    {
        float4 cb0 = *(const float4*)&g_cb[cg * 4];
        float4 cb1 = *(const float4*)&g_cb[64 + cg * 4];
        cb[0] = cb0.x; cb[1] = cb0.y; cb[2] = cb0.z; cb[3] = cb0.w;
        cb[4] = cb1.x; cb[5] = cb1.y; cb[6] = cb1.z; cb[7] = cb1.w;
    }
    const float L2E = 1.4426950408889634f;

#pragma unroll
    for (int i = 0; i < 8; ++i) {
        float hq = -0.5f * xq[i];
        float e[8], m = -3.0e38f;
#pragma unroll
        for (int k = 0; k < 4; ++k) {
            float lo, hi;
            UNPACK2(lo, hi, acc2[i][k]);
            e[k * 2] = lo + hq + cb[k * 2];
            e[k * 2 + 1] = hi + hq + cb[k * 2 + 1];
        }
#pragma unroll
        for (int k = 0; k < 8; ++k) m = fmaxf(m, e[k]);
#pragma unroll
        for (int off = 8; off >= 1; off >>= 1)
            m = fmaxf(m, __shfl_xor_sync(0xffffffffu, m, off, 16));
        float4 o0, o1;
        o0.x = exp2f((e[0] - m) * L2E); o0.y = exp2f((e[1] - m) * L2E);
        o0.z = exp2f((e[2] - m) * L2E); o0.w = exp2f((e[3] - m) * L2E);
        o1.x = exp2f((e[4] - m) * L2E); o1.y = exp2f((e[5] - m) * L2E);
        o1.z = exp2f((e[6] - m) * L2E); o1.w = exp2f((e[7] - m) * L2E);
        size_t row = (size_t)(r0 + rr + 16 * i);
        *(float4*)&g_f[row * NC + cg * 4] = o0;
        *(float4*)&g_f[row * NC + 64 + cg * 4] = o1;
        if (cg == 0) g_mu[row] = m;
    }
}

// ---------- recursion: 16 blocks x 128, matvec on tensor pipe ----------
__global__ __launch_bounds__(128, 1) void rec_kernel(const int* __restrict__ lengths,
                                                     float* __restrict__ out) {
    const int b = blockIdx.x, c = threadIdx.x;
    const int w = c >> 5, lane = c & 31;
    const int g = lane >> 2, tig = lane & 3;
    __shared__ __align__(16) float psh[2][NC];
    __shared__ __align__(8) __nv_bfloat16 psb[2][NC];
    __shared__ float shs[4];

    // A fragments: E rows [32w, 32w+32) as bf16, 2 m-tiles x 8 k-tiles
    unsigned Af[2][8][4];
#pragma unroll
    for (int mt = 0; mt < 2; ++mt) {
        int rA = 32 * w + 16 * mt + g;
        int rB = rA + 8;
#pragma unroll
        for (int kt = 0; kt < 8; ++kt) {
            int k0 = 16 * kt + tig * 2;
            Af[mt][kt][0] = pbf(g_E[rA * NC + k0],     g_E[rA * NC + k0 + 1]);
            Af[mt][kt][1] = pbf(g_E[rB * NC + k0],     g_E[rB * NC + k0 + 1]);
            Af[mt][kt][2] = pbf(g_E[rA * NC + k0 + 8], g_E[rA * NC + k0 + 9]);
            Af[mt][kt][3] = pbf(g_E[rB * NC + k0 + 8], g_E[rB * NC + k0 + 9]);
        }
    }

    float Dr[MAXK];
#pragma unroll
    for (int j = 0; j < MAXK; ++j) Dr[j] = g_dtab[j * NC + c];
    float v[WLEN];
#pragma unroll
    for (int j = 0; j < WLEN; ++j) v[j] = 0.f;

    const int len = lengths[b];
    const float* fp = g_f + (size_t)b * NT * NC;
    const float* mup = g_mu + b * NT;

    float wv = g_winit[c];
    float fr_cur = __ldg(&fp[c]);           // f_0 * rm(=1)
    float al = fr_cur * (wv * Dr[0]);       // alpha_1 (window empty)
    float sigma = __ldg(&mup[0]);
    int ks = 0;
    float rm = 1.0f;
    int kcur = 0;
    float fA = __ldg(&fp[NC + c]),     muA = __ldg(&mup[1]);
    float fB = __ldg(&fp[2 * NC + c]), muB = __ldg(&mup[2]);

    for (int t = 1;; ++t) {
        const int par = t & 1;

        if (t == len) {
            float s = al;
#pragma unroll
            for (int o = 16; o >= 1; o >>= 1)
                s += __shfl_xor_sync(0xffffffffu, s, o);
            if (lane == 0) shs[w] = s;
            __syncthreads();
            if (c == 0) {
                float st = (shs[0] + shs[1]) + (shs[2] + shs[3]);
                out[b] = sigma + (float)ks * 0.6931471805599453f + logf(st);
            }
            break;
        }

        // publish alpha (f32 for max, bf16 for mma), one barrier
        psh[par][c] = al;
        psb[par][c] = __float2bfloat16(al);
        __syncthreads();

        // prefetch row t+2
        int tn = (t + 2 < NT) ? t + 2 : (NT - 1);
        float fN = __ldg(&fp[(size_t)tn * NC + c]);
        float muN = __ldg(&mup[tn]);

        // block max of alpha_t (exponent only), matvec-shadow
        {
            const uint4* pu = (const uint4*)&psh[par][0];
            uint4 q = pu[lane];
            unsigned q01 = q.x > q.y ? q.x : q.y;
            unsigned q23 = q.z > q.w ? q.z : q.w;
            unsigned qm = q01 > q23 ? q01 : q23;
            unsigned mm;
            asm("redux.sync.max.u32 %0, %1, 0xffffffff;" : "=r"(mm) : "r"(qm));
            unsigned e = mm >> 23;
            rm = __uint_as_float((254u - e) << 23);
            kcur = (int)e - 127;
        }

        // window update with fr_cur; uses old wv
#pragma unroll
        for (int j = WLEN - 1; j >= 1; --j) v[j] = v[j - 1] * fr_cur;
        v[0] = wv * fr_cur;

        // duration dot for NEXT alpha
        float d0 = 0.f, d1 = 0.f, d2 = 0.f, d3 = 0.f;
#pragma unroll
        for (int j = 1; j < MAXK; j += 4) {
            d0 = fmaf(v[j - 1], Dr[j], d0);
            if (j + 1 < MAXK) d1 = fmaf(v[j], Dr[j + 1], d1);
            if (j + 2 < MAXK) d2 = fmaf(v[j + 1], Dr[j + 2], d2);
            if (j + 3 < MAXK) d3 = fmaf(v[j + 2], Dr[j + 3], d3);
        }
        float dsum = (d0 + d1) + (d2 + d3);

        // matvec on tensor pipe: wv = E[c,:].alpha via m16n8k16 bf16 HMMA
        {
            const __nv_bfloat16* pbv = &psb[par][0];
            unsigned bfr[8][2];
#pragma unroll
            for (int kt = 0; kt < 8; ++kt) {
                bfr[kt][0] = *(const unsigned*)(pbv + kt * 16 + tig * 2);
                bfr[kt][1] = *(const unsigned*)(pbv + kt * 16 + tig * 2 + 8);
            }
            float dEv[2][4], dOd[2][4];
#pragma unroll
            for (int mt = 0; mt < 2; ++mt)
#pragma unroll
                for (int i = 0; i < 4; ++i) { dEv[mt][i] = 0.f; dOd[mt][i] = 0.f; }
#pragma unroll
            for (int kt = 0; kt < 8; kt += 2) {
                MMA16816(dEv[0], Af[0][kt],     bfr[kt]);
                MMA16816(dOd[0], Af[0][kt + 1], bfr[kt + 1]);
                MMA16816(dEv[1], Af[1][kt],     bfr[kt]);
                MMA16816(dOd[1], Af[1][kt + 1], bfr[kt + 1]);
            }
            float c00 = dEv[0][0] + dOd[0][0];   // wv[32w + g]        (mt0, c0)
            float c20 = dEv[0][2] + dOd[0][2];   // wv[32w + 8 + g]    (mt0, c2)
            float c01 = dEv[1][0] + dOd[1][0];   // wv[32w + 16 + g]   (mt1, c0)
            float c21 = dEv[1][2] + dOd[1][2];   // wv[32w + 24 + g]   (mt1, c2)
            int src = (lane & 7) * 4;
            float w00 = __shfl_sync(0xffffffffu, c00, src);
            float w01 = __shfl_sync(0xffffffffu, c20, src);
            float w10 = __shfl_sync(0xffffffffu, c01, src);
            float w11 = __shfl_sync(0xffffffffu, c21, src);
            int sel = lane >> 3;
            wv = (sel == 0) ? w00 : (sel == 1) ? w01 : (sel == 2) ? w10 : w11;
        }

        // next alpha: 2-op tail after wv
        fr_cur = fA * rm;
        al = fr_cur * fmaf(wv, Dr[0], dsum);
        sigma += muA;
        ks += kcur;

        fA = fB; muA = muB; fB = fN; muB = muN;
    }
}

extern "C" void kernel_launch(void* const* d_in, const int* in_sizes, int n_in,
                              void* d_out, int out_size) {
    const float* feat    = (const float*)d_in[0];
    const int*   lengths = (const int*)d_in[1];
    const float* means   = (const float*)d_in[2];
    const float* cov     = (const float*)d_in[3];
    const float* trans   = (const float*)d_in[4];
    const float* initlg  = (const float*)d_in[5];
    const float* lograte = (const float*)d_in[6];
    float* out = (float*)d_out;

    prep_misc<<<1, 256>>>(means, cov, initlg, lograte);
    prep_trans<<<1, 1024>>>(trans);
    prep_miT<<<32, 256>>>(means, cov);
    emis_kernel<<<256, 256>>>(feat);
    rec_kernel<<<NB, 128>>>(lengths, out);
}

// round 13
// speedup vs baseline: 1.1285x; 1.1285x over previous
#include <cuda_runtime.h>
#include <cuda_bf16.h>
#include <math.h>
#include <stdint.h>

#define NB 16
#define NT 2048
#define ND 256
#define NC 128
#define MAXK 20
#define WLEN 19      // live window elements
#define CHROWS 64    // emission chunk rows
#define NCHUNK (NT / CHROWS)   // 32

typedef unsigned long long ull;

union U2 { float4 f4; ull u[2]; };

#define FMA2(acc, a, b) asm("fma.rn.f32x2 %0, %1, %2, %0;" : "+l"(acc) : "l"(a), "l"(b))
#define PACK2(d, x, y)  asm("mov.b64 %0, {%1, %2};" : "=l"(d) : "f"(x), "f"(y))
#define UNPACK2(x, y, d) asm("mov.b64 {%0, %1}, %2;" : "=f"(x), "=f"(y) : "l"(d))

// ---------- device scratch ----------
__device__ float g_E[NC * NC];        // exp(trans_lp) row-major, diag 0
__device__ float g_winit[NC];         // exp(init_lp)
__device__ float g_dtab[MAXK * NC];   // exp(len_lp[l-1][c])
__device__ float g_miT[ND * NC];      // (means*inv_var)^T  [d][c]
__device__ float g_cb[NC];            // const - 0.5*mq[c]
__device__ float g_iv[ND];            // 1/cov
__device__ float g_f[(size_t)NB * NT * NC]; // exp(emis - rowmax)
__device__ float g_mu[NB * NT];       // rowmax(emis)
__device__ int   g_done[NB * NCHUNK]; // per (batch, chunk) readiness flags

// ---------- prep_misc: 1 block x 256 : iv, cb, winit, dtab, zero flags ----------
__global__ void prep_misc(const float* __restrict__ means,
                          const float* __restrict__ cov,
                          const float* __restrict__ initlg,
                          const float* __restrict__ lograte) {
    const int t = threadIdx.x;
    const int lane = t & 31, w = t >> 5;
    __shared__ float red[8];
    __shared__ float s_cst;
    __shared__ float s_iv[ND];

    // zero readiness flags (512 ints)
    g_done[t] = 0;
    g_done[t + 256] = 0;

    float cv = cov[t];
    float iv = __fdividef(1.0f, cv);
    g_iv[t] = iv;
    s_iv[t] = iv;
    float ls = __logf(cv);
#pragma unroll
    for (int o = 16; o >= 1; o >>= 1)
        ls += __shfl_xor_sync(0xffffffffu, ls, o);
    if (lane == 0) red[w] = ls;
    __syncthreads();
    if (t == 0) {
        float tot = 0.f;
        for (int i = 0; i < 8; ++i) tot += red[i];
        s_cst = -0.5f * (256.0f * 1.8378770664093453f + tot);
    }
    __syncthreads();
    const float cst = s_cst;

    for (int ci = 0; ci < 16; ++ci) {
        int c = ci * 8 + w;
        float p = 0.f;
#pragma unroll
        for (int k = 0; k < 8; ++k) {
            int d = k * 32 + lane;
            float m = means[c * ND + d];
            p = fmaf(m * m, s_iv[d], p);
        }
#pragma unroll
        for (int o = 16; o >= 1; o >>= 1)
            p += __shfl_xor_sync(0xffffffffu, p, o);
        if (lane == 0) g_cb[c] = cst - 0.5f * p;
    }

    if (t < NC) {
        float il = initlg[t];
        float mx = il;
#pragma unroll
        for (int o = 16; o >= 1; o >>= 1)
            mx = fmaxf(mx, __shfl_xor_sync(0xffffffffu, mx, o));
        if (lane == 0) red[w] = mx;
    }
    __syncthreads();
    if (t < NC) {
        float mx = fmaxf(fmaxf(red[0], red[1]), fmaxf(red[2], red[3]));
        float il = initlg[t];
        float ex = __expf(il - mx);
        float s = ex;
#pragma unroll
        for (int o = 16; o >= 1; o >>= 1)
            s += __shfl_xor_sync(0xffffffffu, s, o);
        if (lane == 0) red[4 + w] = s;
        __syncthreads();
        float tot = (red[4] + red[5]) + (red[6] + red[7]);
        g_winit[t] = __fdividef(ex, tot);

        float r = lograte[t];
        float lam = __expf(r);
        float lg = 0.f;
        for (int l = 1; l <= MAXK; ++l) {
            lg += __logf((float)l);
            g_dtab[(l - 1) * NC + t] = __expf(fmaf((float)l, r, -lam) - lg);
        }
    }
}

// ---------- prep_trans: 1 block x 1024 ----------
__global__ __launch_bounds__(1024) void prep_trans(const float* __restrict__ trans) {
    const int t = threadIdx.x;
    const int j = t & 127;
    const int g = t >> 7;
    __shared__ float gmax[8][NC];
    __shared__ float gsum[8][NC];
    __shared__ float colmax[NC], colinv[NC];

    float v[16];
    float mx = -3.0e38f;
#pragma unroll
    for (int k = 0; k < 16; ++k) {
        int i = g * 16 + k;
        float x = trans[i * NC + j];
        if (i == j) x = -1.0e9f;
        v[k] = x;
        mx = fmaxf(mx, x);
    }
    gmax[g][j] = mx;
    __syncthreads();
    if (t < NC) {
        float m = gmax[0][t];
#pragma unroll
        for (int i = 1; i < 8; ++i) m = fmaxf(m, gmax[i][t]);
        colmax[t] = m;
    }
    __syncthreads();
    float cm = colmax[j];
    float ex[16], s = 0.f;
#pragma unroll
    for (int k = 0; k < 16; ++k) {
        ex[k] = __expf(v[k] - cm);
        s += ex[k];
    }
    gsum[g][j] = s;
    __syncthreads();
    if (t < NC) {
        float ss = 0.f;
#pragma unroll
        for (int i = 0; i < 8; ++i) ss += gsum[i][t];
        colinv[t] = __fdividef(1.0f, ss);
    }
    __syncthreads();
    float inv = colinv[j];
#pragma unroll
    for (int k = 0; k < 16; ++k) {
        int i = g * 16 + k;
        g_E[i * NC + j] = (i == j) ? 0.0f : ex[k] * inv;
    }
}

// ---------- prep_miT: 32 blocks x 256 ----------
__global__ void prep_miT(const float* __restrict__ means,
                         const float* __restrict__ cov) {
    __shared__ float tile[32][33];
    const int t = threadIdx.x;
    const int tc = blockIdx.x & 3, td = blockIdx.x >> 2;
    const int c0 = tc * 32, d0 = td * 32;
    const int r = t >> 5, dl = t & 31;

    float iv = __fdividef(1.0f, cov[d0 + dl]);
#pragma unroll
    for (int k = 0; k < 4; ++k) {
        int rr = r + 8 * k;
        tile[rr][dl] = means[(c0 + rr) * ND + d0 + dl] * iv;
    }
    __syncthreads();
#pragma unroll
    for (int k = 0; k < 4; ++k) {
        int dr = r + 8 * k;
        g_miT[(d0 + dr) * NC + c0 + dl] = tile[dl][dr];
    }
}

// ---------- fused kernel: 16 rec blocks + 512 emission producer blocks ----------
__global__ __launch_bounds__(256) void fused_kernel(const float* __restrict__ feat,
                                                    const int* __restrict__ lengths,
                                                    float* __restrict__ out) {
    if (blockIdx.x >= NB) {
        // ================= emission producer: 64 rows =================
        const int eb = blockIdx.x - NB;
        const int chunk = eb >> 4;      // chunk-major: early chunks launch first
        const int b = eb & 15;
        const int r0 = b * NT + chunk * CHROWS;

        __shared__ float A[CHROWS][40];
        __shared__ float Bt[32][132];
        __shared__ float ivs[32];

        const int tid = threadIdx.x;
        const int cg = tid & 15;
        const int rr = tid >> 4;

        ull acc2[4][4];
#pragma unroll
        for (int i = 0; i < 4; ++i)
#pragma unroll
            for (int k = 0; k < 4; ++k) acc2[i][k] = 0ull;
        float xq[4] = {0.f, 0.f, 0.f, 0.f};

        for (int d0 = 0; d0 < ND; d0 += 32) {
            __syncthreads();
            // A tile 64x32 = 512 float4
#pragma unroll
            for (int k = 0; k < 2; ++k) {
                int i = tid + k * 256;
                int row = i >> 3, q = i & 7;
                *(float4*)&A[row][q * 4] =
                    *(const float4*)&feat[(size_t)(r0 + row) * ND + d0 + q * 4];
            }
            // Bt tile 32x128 = 1024 float4
#pragma unroll
            for (int k = 0; k < 4; ++k) {
                int i = tid + k * 256;
                int drow = i >> 5, q = i & 31;
                *(float4*)&Bt[drow][q * 4] =
                    *(const float4*)&g_miT[(size_t)(d0 + drow) * NC + q * 4];
            }
            if (tid < 32) ivs[tid] = g_iv[d0 + tid];
            __syncthreads();

#pragma unroll
            for (int u = 0; u < 2; ++u) {
                int dd = cg + u * 16;
                float iv = ivs[dd];
#pragma unroll
                for (int i = 0; i < 4; ++i) {
                    float a = A[rr + 16 * i][dd];
                    xq[i] = fmaf(a * iv, a, xq[i]);
                }
            }

#pragma unroll 8
            for (int dd = 0; dd < 32; ++dd) {
                U2 b0, b1;
                b0.f4 = *(const float4*)&Bt[dd][cg * 4];
                b1.f4 = *(const float4*)&Bt[dd][64 + cg * 4];
#pragma unroll
                for (int i = 0; i < 4; ++i) {
                    float a = A[rr + 16 * i][dd];
                    ull aa;
                    PACK2(aa, a, a);
                    FMA2(acc2[i][0], aa, b0.u[0]);
                    FMA2(acc2[i][1], aa, b0.u[1]);
                    FMA2(acc2[i][2], aa, b1.u[0]);
                    FMA2(acc2[i][3], aa, b1.u[1]);
                }
            }
        }

#pragma unroll
        for (int o = 1; o < 16; o <<= 1) {
#pragma unroll
            for (int i = 0; i < 4; ++i)
                xq[i] += __shfl_xor_sync(0xffffffffu, xq[i], o, 16);
        }

        float cb[8];
        {
            float4 cb0 = *(const float4*)&g_cb[cg * 4];
            float4 cb1 = *(const float4*)&g_cb[64 + cg * 4];
            cb[0] = cb0.x; cb[1] = cb0.y; cb[2] = cb0.z; cb[3] = cb0.w;
            cb[4] = cb1.x; cb[5] = cb1.y; cb[6] = cb1.z; cb[7] = cb1.w;
        }
        const float L2E = 1.4426950408889634f;

#pragma unroll
        for (int i = 0; i < 4; ++i) {
            float hq = -0.5f * xq[i];
            float e[8], m = -3.0e38f;
#pragma unroll
            for (int k = 0; k < 4; ++k) {
                float lo, hi;
                UNPACK2(lo, hi, acc2[i][k]);
                e[k * 2] = lo + hq + cb[k * 2];
                e[k * 2 + 1] = hi + hq + cb[k * 2 + 1];
            }
#pragma unroll
            for (int k = 0; k < 8; ++k) m = fmaxf(m, e[k]);
#pragma unroll
            for (int off = 8; off >= 1; off >>= 1)
                m = fmaxf(m, __shfl_xor_sync(0xffffffffu, m, off, 16));
            float4 o0, o1;
            o0.x = exp2f((e[0] - m) * L2E); o0.y = exp2f((e[1] - m) * L2E);
            o0.z = exp2f((e[2] - m) * L2E); o0.w = exp2f((e[3] - m) * L2E);
            o1.x = exp2f((e[4] - m) * L2E); o1.y = exp2f((e[5] - m) * L2E);
            o1.z = exp2f((e[6] - m) * L2E); o1.w = exp2f((e[7] - m) * L2E);
            size_t row = (size_t)(r0 + rr + 16 * i);
            *(float4*)&g_f[row * NC + cg * 4] = o0;
            *(float4*)&g_f[row * NC + 64 + cg * 4] = o1;
            if (cg == 0) g_mu[row] = m;
        }

        // publish chunk
        __threadfence();
        __syncthreads();
        if (tid == 0) atomicExch(&g_done[b * NCHUNK + chunk], 1);
        return;
    }

    // ================= recursion consumer (R11 structure) =================
    if (threadIdx.x >= 128) return;   // exited threads count as arrived at bar

    const int b = blockIdx.x, c = threadIdx.x;
    const int w = c >> 5, lane = c & 31;
    __shared__ __align__(16) float psh[2][NC];
    __shared__ float shs[4];

    ull Er2[64];
#pragma unroll
    for (int k = 0; k < 32; ++k) {
        U2 u;
        u.f4 = *(const float4*)&g_E[c * NC + k * 4];
        Er2[k * 2] = u.u[0];
        Er2[k * 2 + 1] = u.u[1];
    }
    float Dr[MAXK];
#pragma unroll
    for (int j = 0; j < MAXK; ++j) Dr[j] = g_dtab[j * NC + c];
    float v[WLEN];
#pragma unroll
    for (int j = 0; j < WLEN; ++j) v[j] = 0.f;

    const int len = lengths[b];
    const float* fp = g_f + (size_t)b * NT * NC;
    const float* mup = g_mu + b * NT;

    int qready = -1;
#define WAIT_CHUNK(q)                                                        \
    if ((q) > qready) {                                                      \
        const int* fl = &g_done[b * NCHUNK + (q)];                           \
        int d_;                                                              \
        do {                                                                 \
            asm volatile("ld.global.cg.b32 %0, [%1];" : "=r"(d_) : "l"(fl) : "memory"); \
            if (!d_) __nanosleep(64);                                        \
        } while (!d_);                                                       \
        qready = (q);                                                        \
        __threadfence();                                                     \
    }

    WAIT_CHUNK(0);

    float wv = g_winit[c];
    float fr_cur = __ldg(&fp[c]);           // f_0 * rm(=1)
    float al = fr_cur * (wv * Dr[0]);       // alpha_1 (window empty)
    float sigma = __ldg(&mup[0]);
    int ks = 0;
    float rm = 1.0f;
    int kcur = 0;
    float fA = __ldg(&fp[NC + c]),     muA = __ldg(&mup[1]);
    float fB = __ldg(&fp[2 * NC + c]), muB = __ldg(&mup[2]);

    for (int t = 1;; ++t) {
        const int par = t & 1;

        if (t == len) {
            float s = al;
#pragma unroll
            for (int o = 16; o >= 1; o >>= 1)
                s += __shfl_xor_sync(0xffffffffu, s, o);
            if (lane == 0) shs[w] = s;
            __syncthreads();
            if (c == 0) {
                float st = (shs[0] + shs[1]) + (shs[2] + shs[3]);
                out[b] = sigma + (float)ks * 0.6931471805599453f + logf(st);
            }
            break;
        }

        // minimal pre-barrier chain: publish alpha, barrier
        psh[par][c] = al;
        __syncthreads();

        // prefetch row t+2 (wait for its chunk first; nearly always ready)
        int tn = (t + 2 < NT) ? t + 2 : (NT - 1);
        WAIT_CHUNK(tn >> 6);
        float fN = __ldg(&fp[(size_t)tn * NC + c]);
        float muN = __ldg(&mup[tn]);

        // block max of alpha_t (exponent only), matvec-shadow
        {
            const uint4* pu = (const uint4*)&psh[par][0];
            uint4 q = pu[lane];
            unsigned q01 = q.x > q.y ? q.x : q.y;
            unsigned q23 = q.z > q.w ? q.z : q.w;
            unsigned qm = q01 > q23 ? q01 : q23;
            unsigned mm;
            asm("redux.sync.max.u32 %0, %1, 0xffffffff;" : "=r"(mm) : "r"(qm));
            unsigned e = mm >> 23;
            rm = __uint_as_float((254u - e) << 23);     // 2^(127-e)
            kcur = (int)e - 127;
        }

        // window update with fr_cur; uses old wv (19 live elements)
#pragma unroll
        for (int j = WLEN - 1; j >= 1; --j) v[j] = v[j - 1] * fr_cur;
        v[0] = wv * fr_cur;

        // duration dot for NEXT alpha (independent of new wv)
        float d0 = 0.f, d1 = 0.f, d2 = 0.f, d3 = 0.f;
#pragma unroll
        for (int j = 1; j < MAXK; j += 4) {
            d0 = fmaf(v[j - 1], Dr[j], d0);
            if (j + 1 < MAXK) d1 = fmaf(v[j], Dr[j + 1], d1);
            if (j + 2 < MAXK) d2 = fmaf(v[j + 1], Dr[j + 2], d2);
            if (j + 3 < MAXK) d3 = fmaf(v[j + 2], Dr[j + 3], d3);
        }
        float dsum = (d0 + d1) + (d2 + d3);

        // full-row matvec on unnormalized alpha
        const float* pb = &psh[par][0];
        ull a0 = 0ull, a1 = 0ull, a2 = 0ull, a3 = 0ull;
#pragma unroll
        for (int k = 0; k < 32; k += 2) {
            U2 p0, p1;
            p0.f4 = *(const float4*)&pb[k * 4];
            p1.f4 = *(const float4*)&pb[k * 4 + 4];
            FMA2(a0, Er2[k * 2], p0.u[0]);
            FMA2(a1, Er2[k * 2 + 1], p0.u[1]);
            FMA2(a2, Er2[k * 2 + 2], p1.u[0]);
            FMA2(a3, Er2[k * 2 + 3], p1.u[1]);
        }
        float x0, y0, x1, y1, x2, y2, x3, y3;
        UNPACK2(x0, y0, a0); UNPACK2(x1, y1, a1);
        UNPACK2(x2, y2, a2); UNPACK2(x3, y3, a3);
        wv = ((x0 + y0) + (x1 + y1)) + ((x2 + y2) + (x3 + y3));

        // next alpha: 2-op tail after wv
        fr_cur = fA * rm;
        al = fr_cur * fmaf(wv, Dr[0], dsum);
        sigma += muA;
        ks += kcur;

        fA = fB; muA = muB; fB = fN; muB = muN;
    }
#undef WAIT_CHUNK
}

extern "C" void kernel_launch(void* const* d_in, const int* in_sizes, int n_in,
                              void* d_out, int out_size) {
    const float* feat    = (const float*)d_in[0];
    const int*   lengths = (const int*)d_in[1];
    const float* means   = (const float*)d_in[2];
    const float* cov     = (const float*)d_in[3];
    const float* trans   = (const float*)d_in[4];
    const float* initlg  = (const float*)d_in[5];
    const float* lograte = (const float*)d_in[6];
    float* out = (float*)d_out;

    prep_misc<<<1, 256>>>(means, cov, initlg, lograte);
    prep_trans<<<1, 1024>>>(trans);
    prep_miT<<<32, 256>>>(means, cov);
    fused_kernel<<<NB + NB * NCHUNK, 256>>>(feat, lengths, out);
}

// round 14
// speedup vs baseline: 1.2739x; 1.1289x over previous
#include <cuda_runtime.h>
#include <cuda_bf16.h>
#include <math.h>
#include <stdint.h>

#define NB 16
#define NT 2048
#define ND 256
#define NC 128
#define MAXK 20
#define WLEN 19      // live window elements
#define CHROWS 64    // emission chunk rows
#define NCHUNK (NT / CHROWS)   // 32

typedef unsigned long long ull;

union U2 { float4 f4; ull u[2]; };

#define FMA2(acc, a, b) asm("fma.rn.f32x2 %0, %1, %2, %0;" : "+l"(acc) : "l"(a), "l"(b))
#define PACK2(d, x, y)  asm("mov.b64 %0, {%1, %2};" : "=l"(d) : "f"(x), "f"(y))
#define UNPACK2(x, y, d) asm("mov.b64 {%0, %1}, %2;" : "=f"(x), "=f"(y) : "l"(d))
#define HFMA2BF(acc, a, b) asm("fma.rn.bf16x2 %0, %1, %2, %0;" : "+r"(acc) : "r"(a), "r"(b))

// ---------- device scratch ----------
__device__ float g_E[NC * NC];        // exp(trans_lp) row-major, diag 0
__device__ float g_winit[NC];         // exp(init_lp)
__device__ float g_dtab[MAXK * NC];   // exp(len_lp[l-1][c])
__device__ float g_miT[ND * NC];      // (means*inv_var)^T  [d][c]
__device__ float g_cb[NC];            // const - 0.5*mq[c]
__device__ float g_iv[ND];            // 1/cov
__device__ float g_f[(size_t)NB * NT * NC]; // exp(emis - rowmax)
__device__ float g_mu[NB * NT];       // rowmax(emis)
__device__ int   g_done[NB * NCHUNK]; // per (batch, chunk) readiness flags

// ---------- prep_misc: 1 block x 256 : iv, cb, winit, dtab, zero flags ----------
__global__ void prep_misc(const float* __restrict__ means,
                          const float* __restrict__ cov,
                          const float* __restrict__ initlg,
                          const float* __restrict__ lograte) {
    const int t = threadIdx.x;
    const int lane = t & 31, w = t >> 5;
    __shared__ float red[8];
    __shared__ float s_cst;
    __shared__ float s_iv[ND];

    // zero readiness flags (512 ints)
    g_done[t] = 0;
    g_done[t + 256] = 0;

    float cv = cov[t];
    float iv = __fdividef(1.0f, cv);
    g_iv[t] = iv;
    s_iv[t] = iv;
    float ls = __logf(cv);
#pragma unroll
    for (int o = 16; o >= 1; o >>= 1)
        ls += __shfl_xor_sync(0xffffffffu, ls, o);
    if (lane == 0) red[w] = ls;
    __syncthreads();
    if (t == 0) {
        float tot = 0.f;
        for (int i = 0; i < 8; ++i) tot += red[i];
        s_cst = -0.5f * (256.0f * 1.8378770664093453f + tot);
    }
    __syncthreads();
    const float cst = s_cst;

    for (int ci = 0; ci < 16; ++ci) {
        int c = ci * 8 + w;
        float p = 0.f;
#pragma unroll
        for (int k = 0; k < 8; ++k) {
            int d = k * 32 + lane;
            float m = means[c * ND + d];
            p = fmaf(m * m, s_iv[d], p);
        }
#pragma unroll
        for (int o = 16; o >= 1; o >>= 1)
            p += __shfl_xor_sync(0xffffffffu, p, o);
        if (lane == 0) g_cb[c] = cst - 0.5f * p;
    }

    if (t < NC) {
        float il = initlg[t];
        float mx = il;
#pragma unroll
        for (int o = 16; o >= 1; o >>= 1)
            mx = fmaxf(mx, __shfl_xor_sync(0xffffffffu, mx, o));
        if (lane == 0) red[w] = mx;
    }
    __syncthreads();
    if (t < NC) {
        float mx = fmaxf(fmaxf(red[0], red[1]), fmaxf(red[2], red[3]));
        float il = initlg[t];
        float ex = __expf(il - mx);
        float s = ex;
#pragma unroll
        for (int o = 16; o >= 1; o >>= 1)
            s += __shfl_xor_sync(0xffffffffu, s, o);
        if (lane == 0) red[4 + w] = s;
        __syncthreads();
        float tot = (red[4] + red[5]) + (red[6] + red[7]);
        g_winit[t] = __fdividef(ex, tot);

        float r = lograte[t];
        float lam = __expf(r);
        float lg = 0.f;
        for (int l = 1; l <= MAXK; ++l) {
            lg += __logf((float)l);
            g_dtab[(l - 1) * NC + t] = __expf(fmaf((float)l, r, -lam) - lg);
        }
    }
}

// ---------- prep_trans: 1 block x 1024 ----------
__global__ __launch_bounds__(1024) void prep_trans(const float* __restrict__ trans) {
    const int t = threadIdx.x;
    const int j = t & 127;
    const int g = t >> 7;
    __shared__ float gmax[8][NC];
    __shared__ float gsum[8][NC];
    __shared__ float colmax[NC], colinv[NC];

    float v[16];
    float mx = -3.0e38f;
#pragma unroll
    for (int k = 0; k < 16; ++k) {
        int i = g * 16 + k;
        float x = trans[i * NC + j];
        if (i == j) x = -1.0e9f;
        v[k] = x;
        mx = fmaxf(mx, x);
    }
    gmax[g][j] = mx;
    __syncthreads();
    if (t < NC) {
        float m = gmax[0][t];
#pragma unroll
        for (int i = 1; i < 8; ++i) m = fmaxf(m, gmax[i][t]);
        colmax[t] = m;
    }
    __syncthreads();
    float cm = colmax[j];
    float ex[16], s = 0.f;
#pragma unroll
    for (int k = 0; k < 16; ++k) {
        ex[k] = __expf(v[k] - cm);
        s += ex[k];
    }
    gsum[g][j] = s;
    __syncthreads();
    if (t < NC) {
        float ss = 0.f;
#pragma unroll
        for (int i = 0; i < 8; ++i) ss += gsum[i][t];
        colinv[t] = __fdividef(1.0f, ss);
    }
    __syncthreads();
    float inv = colinv[j];
#pragma unroll
    for (int k = 0; k < 16; ++k) {
        int i = g * 16 + k;
        g_E[i * NC + j] = (i == j) ? 0.0f : ex[k] * inv;
    }
}

// ---------- prep_miT: 32 blocks x 256 ----------
__global__ void prep_miT(const float* __restrict__ means,
                         const float* __restrict__ cov) {
    __shared__ float tile[32][33];
    const int t = threadIdx.x;
    const int tc = blockIdx.x & 3, td = blockIdx.x >> 2;
    const int c0 = tc * 32, d0 = td * 32;
    const int r = t >> 5, dl = t & 31;

    float iv = __fdividef(1.0f, cov[d0 + dl]);
#pragma unroll
    for (int k = 0; k < 4; ++k) {
        int rr = r + 8 * k;
        tile[rr][dl] = means[(c0 + rr) * ND + d0 + dl] * iv;
    }
    __syncthreads();
#pragma unroll
    for (int k = 0; k < 4; ++k) {
        int dr = r + 8 * k;
        g_miT[(d0 + dr) * NC + c0 + dl] = tile[dl][dr];
    }
}

// ---------- fused kernel: 16 rec blocks + 512 emission producer blocks ----------
__global__ __launch_bounds__(256) void fused_kernel(const float* __restrict__ feat,
                                                    const int* __restrict__ lengths,
                                                    float* __restrict__ out) {
    if (blockIdx.x >= NB) {
        // ================= emission producer: 64 rows =================
        const int eb = blockIdx.x - NB;
        const int chunk = eb >> 4;      // chunk-major: early chunks launch first
        const int b = eb & 15;
        const int r0 = b * NT + chunk * CHROWS;

        __shared__ float A[CHROWS][40];
        __shared__ float Bt[32][132];
        __shared__ float ivs[32];

        const int tid = threadIdx.x;
        const int cg = tid & 15;
        const int rr = tid >> 4;

        ull acc2[4][4];
#pragma unroll
        for (int i = 0; i < 4; ++i)
#pragma unroll
            for (int k = 0; k < 4; ++k) acc2[i][k] = 0ull;
        float xq[4] = {0.f, 0.f, 0.f, 0.f};

        for (int d0 = 0; d0 < ND; d0 += 32) {
            __syncthreads();
#pragma unroll
            for (int k = 0; k < 2; ++k) {
                int i = tid + k * 256;
                int row = i >> 3, q = i & 7;
                *(float4*)&A[row][q * 4] =
                    *(const float4*)&feat[(size_t)(r0 + row) * ND + d0 + q * 4];
            }
#pragma unroll
            for (int k = 0; k < 4; ++k) {
                int i = tid + k * 256;
                int drow = i >> 5, q = i & 31;
                *(float4*)&Bt[drow][q * 4] =
                    *(const float4*)&g_miT[(size_t)(d0 + drow) * NC + q * 4];
            }
            if (tid < 32) ivs[tid] = g_iv[d0 + tid];
            __syncthreads();

#pragma unroll
            for (int u = 0; u < 2; ++u) {
                int dd = cg + u * 16;
                float iv = ivs[dd];
#pragma unroll
                for (int i = 0; i < 4; ++i) {
                    float a = A[rr + 16 * i][dd];
                    xq[i] = fmaf(a * iv, a, xq[i]);
                }
            }

#pragma unroll 8
            for (int dd = 0; dd < 32; ++dd) {
                U2 b0, b1;
                b0.f4 = *(const float4*)&Bt[dd][cg * 4];
                b1.f4 = *(const float4*)&Bt[dd][64 + cg * 4];
#pragma unroll
                for (int i = 0; i < 4; ++i) {
                    float a = A[rr + 16 * i][dd];
                    ull aa;
                    PACK2(aa, a, a);
                    FMA2(acc2[i][0], aa, b0.u[0]);
                    FMA2(acc2[i][1], aa, b0.u[1]);
                    FMA2(acc2[i][2], aa, b1.u[0]);
                    FMA2(acc2[i][3], aa, b1.u[1]);
                }
            }
        }

#pragma unroll
        for (int o = 1; o < 16; o <<= 1) {
#pragma unroll
            for (int i = 0; i < 4; ++i)
                xq[i] += __shfl_xor_sync(0xffffffffu, xq[i], o, 16);
        }

        float cb[8];
        {
            float4 cb0 = *(const float4*)&g_cb[cg * 4];
            float4 cb1 = *(const float4*)&g_cb[64 + cg * 4];
            cb[0] = cb0.x; cb[1] = cb0.y; cb[2] = cb0.z; cb[3] = cb0.w;
            cb[4] = cb1.x; cb[5] = cb1.y; cb[6] = cb1.z; cb[7] = cb1.w;
        }
        const float L2E = 1.4426950408889634f;

#pragma unroll
        for (int i = 0; i < 4; ++i) {
            float hq = -0.5f * xq[i];
            float e[8], m = -3.0e38f;
#pragma unroll
            for (int k = 0; k < 4; ++k) {
                float lo, hi;
                UNPACK2(lo, hi, acc2[i][k]);
                e[k * 2] = lo + hq + cb[k * 2];
                e[k * 2 + 1] = hi + hq + cb[k * 2 + 1];
            }
#pragma unroll
            for (int k = 0; k < 8; ++k) m = fmaxf(m, e[k]);
#pragma unroll
            for (int off = 8; off >= 1; off >>= 1)
                m = fmaxf(m, __shfl_xor_sync(0xffffffffu, m, off, 16));
            float4 o0, o1;
            o0.x = exp2f((e[0] - m) * L2E); o0.y = exp2f((e[1] - m) * L2E);
            o0.z = exp2f((e[2] - m) * L2E); o0.w = exp2f((e[3] - m) * L2E);
            o1.x = exp2f((e[4] - m) * L2E); o1.y = exp2f((e[5] - m) * L2E);
            o1.z = exp2f((e[6] - m) * L2E); o1.w = exp2f((e[7] - m) * L2E);
            size_t row = (size_t)(r0 + rr + 16 * i);
            *(float4*)&g_f[row * NC + cg * 4] = o0;
            *(float4*)&g_f[row * NC + 64 + cg * 4] = o1;
            if (cg == 0) g_mu[row] = m;
        }

        // publish chunk
        __threadfence();
        __syncthreads();
        if (tid == 0) atomicExch(&g_done[b * NCHUNK + chunk], 1);
        return;
    }

    // ================= recursion consumer (bf16 matvec) =================
    if (threadIdx.x >= 128) return;   // exited threads count as arrived at bar

    const int b = blockIdx.x, c = threadIdx.x;
    const int w = c >> 5, lane = c & 31;
    __shared__ __align__(16) unsigned short psb[2][NC];  // alpha as bf16
    __shared__ float shs[4];

    // E row as bf16x2: 64 regs
    unsigned Eb[64];
#pragma unroll
    for (int k = 0; k < 64; ++k) {
        __nv_bfloat162 t2 = __floats2bfloat162_rn(g_E[c * NC + 2 * k],
                                                  g_E[c * NC + 2 * k + 1]);
        Eb[k] = *(unsigned*)&t2;
    }
    float Dr[MAXK];
#pragma unroll
    for (int j = 0; j < MAXK; ++j) Dr[j] = g_dtab[j * NC + c];
    float v[WLEN];
#pragma unroll
    for (int j = 0; j < WLEN; ++j) v[j] = 0.f;

    const int len = lengths[b];
    const float* fp = g_f + (size_t)b * NT * NC;
    const float* mup = g_mu + b * NT;

    int qready = -1;
#define WAIT_CHUNK(q)                                                        \
    if ((q) > qready) {                                                      \
        const int* fl = &g_done[b * NCHUNK + (q)];                           \
        int d_;                                                              \
        do {                                                                 \
            asm volatile("ld.global.cg.b32 %0, [%1];" : "=r"(d_) : "l"(fl) : "memory"); \
            if (!d_) __nanosleep(64);                                        \
        } while (!d_);                                                       \
        qready = (q);                                                        \
        __threadfence();                                                     \
    }

    WAIT_CHUNK(0);

    float wv = g_winit[c];
    float fr_cur = __ldg(&fp[c]);           // f_0 * rm(=1)
    float al = fr_cur * (wv * Dr[0]);       // alpha_1 (window empty)
    float sigma = __ldg(&mup[0]);
    int ks = 0;
    float rm = 1.0f;
    int kcur = 0;
    float fA = __ldg(&fp[NC + c]),     muA = __ldg(&mup[1]);
    float fB = __ldg(&fp[2 * NC + c]), muB = __ldg(&mup[2]);

    for (int t = 1;; ++t) {
        const int par = t & 1;

        if (t == len) {
            float s = al;
#pragma unroll
            for (int o = 16; o >= 1; o >>= 1)
                s += __shfl_xor_sync(0xffffffffu, s, o);
            if (lane == 0) shs[w] = s;
            __syncthreads();
            if (c == 0) {
                float st = (shs[0] + shs[1]) + (shs[2] + shs[3]);
                out[b] = sigma + (float)ks * 0.6931471805599453f + logf(st);
            }
            break;
        }

        // minimal pre-barrier chain: publish alpha (bf16), barrier
        {
            __nv_bfloat16 ab = __float2bfloat16(al);
            psb[par][c] = *(unsigned short*)&ab;
        }
        __syncthreads();

        // prefetch row t+2 (wait for its chunk first; nearly always ready)
        int tn = (t + 2 < NT) ? t + 2 : (NT - 1);
        WAIT_CHUNK(tn >> 6);
        float fN = __ldg(&fp[(size_t)tn * NC + c]);
        float muN = __ldg(&mup[tn]);

        // block max of alpha_t from psb (bf16 -> f32 bit space), exponent only
        {
            uint2 q2 = ((const uint2*)&psb[par][0])[lane];
            unsigned v0 = q2.x << 16, v1 = q2.x & 0xffff0000u;
            unsigned v2 = q2.y << 16, v3 = q2.y & 0xffff0000u;
            unsigned m01 = v0 > v1 ? v0 : v1;
            unsigned m23 = v2 > v3 ? v2 : v3;
            unsigned qm = m01 > m23 ? m01 : m23;
            unsigned mm;
            asm("redux.sync.max.u32 %0, %1, 0xffffffff;" : "=r"(mm) : "r"(qm));
            unsigned e = mm >> 23;
            rm = __uint_as_float((254u - e) << 23);     // 2^(127-e)
            kcur = (int)e - 127;
        }

        // window update with fr_cur; uses old wv (19 live elements)
#pragma unroll
        for (int j = WLEN - 1; j >= 1; --j) v[j] = v[j - 1] * fr_cur;
        v[0] = wv * fr_cur;

        // duration dot for NEXT alpha (independent of new wv)
        float d0 = 0.f, d1 = 0.f, d2 = 0.f, d3 = 0.f;
#pragma unroll
        for (int j = 1; j < MAXK; j += 4) {
            d0 = fmaf(v[j - 1], Dr[j], d0);
            if (j + 1 < MAXK) d1 = fmaf(v[j], Dr[j + 1], d1);
            if (j + 2 < MAXK) d2 = fmaf(v[j + 1], Dr[j + 2], d2);
            if (j + 3 < MAXK) d3 = fmaf(v[j + 2], Dr[j + 3], d3);
        }
        float dsum = (d0 + d1) + (d2 + d3);

        // full-row matvec in bf16: wv = E[c,:].alpha
        {
            const uint4* pb4 = (const uint4*)&psb[par][0];
            unsigned a0 = 0u, a1 = 0u, a2 = 0u, a3 = 0u;
#pragma unroll
            for (int kk = 0; kk < 16; ++kk) {
                uint4 q = pb4[kk];
                HFMA2BF(a0, Eb[4 * kk + 0], q.x);
                HFMA2BF(a1, Eb[4 * kk + 1], q.y);
                HFMA2BF(a2, Eb[4 * kk + 2], q.z);
                HFMA2BF(a3, Eb[4 * kk + 3], q.w);
            }
            float f0 = __uint_as_float(a0 << 16) + __uint_as_float(a0 & 0xffff0000u);
            float f1 = __uint_as_float(a1 << 16) + __uint_as_float(a1 & 0xffff0000u);
            float f2 = __uint_as_float(a2 << 16) + __uint_as_float(a2 & 0xffff0000u);
            float f3 = __uint_as_float(a3 << 16) + __uint_as_float(a3 & 0xffff0000u);
            wv = (f0 + f1) + (f2 + f3);
        }

        // next alpha: 2-op tail after wv
        fr_cur = fA * rm;
        al = fr_cur * fmaf(wv, Dr[0], dsum);
        sigma += muA;
        ks += kcur;

        fA = fB; muA = muB; fB = fN; muB = muN;
    }
#undef WAIT_CHUNK
}

extern "C" void kernel_launch(void* const* d_in, const int* in_sizes, int n_in,
                              void* d_out, int out_size) {
    const float* feat    = (const float*)d_in[0];
    const int*   lengths = (const int*)d_in[1];
    const float* means   = (const float*)d_in[2];
    const float* cov     = (const float*)d_in[3];
    const float* trans   = (const float*)d_in[4];
    const float* initlg  = (const float*)d_in[5];
    const float* lograte = (const float*)d_in[6];
    float* out = (float*)d_out;

    prep_misc<<<1, 256>>>(means, cov, initlg, lograte);
    prep_trans<<<1, 1024>>>(trans);
    prep_miT<<<32, 256>>>(means, cov);
    fused_kernel<<<NB + NB * NCHUNK, 256>>>(feat, lengths, out);
}